// round 15
// baseline (speedup 1.0000x reference)
#include <cuda_runtime.h>
#include <cuda_bf16.h>
#include <cstdint>

#define B_ 256
#define L_ 512
#define H_ 768
#define K_ 64
#define M_ (B_*L_)

#define LOG2E 1.4426950408889634f
#define LN2   0.6931471805599453f
#define ESHIFT 6.0f

// -------- device scratch --------
__device__ float          g_emit2[M_*K_];     // emit * log2(e)
__device__ float          g_Tt2[K_*K_];       // Tt2[j][k] = T[k][j]*log2e (gold score)
__device__ float          g_Et[K_*K_];        // Et[j][i]  = 2^(T[i][j]*log2e - 6)
__device__ __nv_bfloat16  g_Wt[K_*H_];        // W^T bf16 [n][h]
__device__ int            g_tags[M_];
__device__ int            g_len[B_];
__device__ int            g_cnt[B_];          // per-batch tile completion counter

__device__ __forceinline__ float ex2f(float x){ float y; asm("ex2.approx.ftz.f32 %0, %1;" : "=f"(y) : "f"(x)); return y; }
__device__ __forceinline__ float lg2f(float x){ float y; asm("lg2.approx.f32 %0, %1;"     : "=f"(y) : "f"(x)); return y; }
__device__ __forceinline__ float rcpf(float x){ float y; asm("rcp.approx.ftz.f32 %0, %1;" : "=f"(y) : "f"(x)); return y; }
#define BAR64() asm volatile("bar.sync 1, 64;" ::: "memory")

#define CP_ASYNC16(sa, gp) asm volatile("cp.async.cg.shared.global [%0], [%1], 16;" :: "r"(sa), "l"(gp) : "memory")
#define CP_COMMIT()        asm volatile("cp.async.commit_group;" ::: "memory")
#define CP_WAIT1()         asm volatile("cp.async.wait_group 1;" ::: "memory")

__device__ __forceinline__ void ldsm_x4(uint32_t& r0, uint32_t& r1, uint32_t& r2, uint32_t& r3,
                                        uint32_t addr)
{
    asm volatile("ldmatrix.sync.aligned.m8n8.x4.shared.b16 {%0,%1,%2,%3}, [%4];"
                 : "=r"(r0), "=r"(r1), "=r"(r2), "=r"(r3) : "r"(addr));
}

// ---------------------------------------------------------------
// convert: self-detect dtypes, canonicalize tags, lengths, W/T prep.
__global__ __launch_bounds__(256)
void convert_kernel(const int* __restrict__ tagsraw,
                    const unsigned char* __restrict__ maskraw,
                    const float* __restrict__ W,
                    const float* __restrict__ T)
{
    __shared__ int s_red[8];
    const int b   = blockIdx.x;
    const int tid = threadIdx.x;

    if (tid == 0) g_cnt[b] = 0;            // reset handoff counters every replay

    // dtype self-detect (first 512 tag words, in-bounds under both dtypes)
    unsigned int w = ((const unsigned int*)tagsraw)[2 * tid + 1];
    const int tm = __syncthreads_or(w != 0) ? 0 : 1;
    const int mm = (maskraw[1] != 0) ? 0 : 1;

    for (int t = tid; t < L_; t += 256) {
        long idx = (long)b * L_ + t;
        g_tags[idx] = (tm == 1) ? tagsraw[2 * idx] : tagsraw[idx];
    }
    int cnt = 0;
    if (mm == 0) {
        const unsigned char* mb = maskraw + (size_t)b * L_;
        for (int t = tid; t < L_; t += 256) cnt += (mb[t] != 0);
    } else {
        const unsigned int* mw = ((const unsigned int*)maskraw) + (size_t)b * L_;
        for (int t = tid; t < L_; t += 256) cnt += (mw[t] != 0);
    }
#pragma unroll
    for (int o = 16; o > 0; o >>= 1) cnt += __shfl_xor_sync(0xffffffffu, cnt, o);
    if ((tid & 31) == 0) s_red[tid >> 5] = cnt;
    __syncthreads();
    if (tid == 0) {
        int s = 0;
#pragma unroll
        for (int i = 0; i < 8; ++i) s += s_red[i];
        g_len[b] = s;
    }

    // ---- prep, strided across the whole grid ----
    const int gidx    = b * 256 + tid;
    const int gstride = B_ * 256;
    for (int i = gidx; i < K_*H_; i += gstride) {
        int n = i / H_, h = i - n*H_;
        g_Wt[i] = __float2bfloat16(W[h*K_ + n]);
    }
    for (int i = gidx; i < K_*K_; i += gstride) {
        int j = i >> 6, k = i & 63;
        float t2 = T[k*K_ + j] * LOG2E;
        g_Tt2[i] = t2;
        g_Et[i]  = ex2f(t2 - ESHIFT);
    }
}

// ---------------------------------------------------------------
// FUSED kernel: GEMM with A loaded DIRECTLY into mma fragments (no A smem,
// no A barrier dependency). 8 warps, warp tile 16x64 (each warp owns 16
// distinct M rows -> zero A duplication; per-lane LDG.64 hits full 32B
// sectors). B: cp.async 3-stage smem + ldmatrix (R11-proven). Blocks
// 4b..4b+3 cover batch b; owner runs the proven 64-thread CRF.
#define BM      128
#define BK      64
#define NITER   (H_/BK)   // 12
#define APITCH  72        // bf16 per smem row (144B)
#define BSTAGE  (K_*APITCH)
#define SMEM_DYN (3*BSTAGE*2)   // 27648 B (B tiles only)

__global__ __launch_bounds__(256, 2)
void fused_kernel(const float* __restrict__ F, const float* __restrict__ bias,
                  float* __restrict__ out)
{
    extern __shared__ __nv_bfloat16 smx[];
    __shared__ float s_red[8];
    __shared__ float ds0[K_], ds1[K_];
    __shared__ float s_score;
    __shared__ int   s_owner;

    __nv_bfloat16* BshB = smx;      // 3 stages K_ x BK

    const int tid  = threadIdx.x;
    const int lane = tid & 31;
    const int warp = tid >> 5;      // 0..7, owns rows warp*16..+15
    const int rowBase = blockIdx.x * BM;

    // ================= GEMM phase =================
    {
        float acc[8][4];
#pragma unroll
        for (int ni = 0; ni < 8; ++ni)
#pragma unroll
            for (int q = 0; q < 4; ++q) acc[ni][q] = 0.f;

        const int g  = lane >> 2;   // fragment row within 8
        const int tq = lane & 3;    // fragment col quad

        // A per-lane base: rows (warp*16 + g) and +8; col pairs tq*2, tq*2+8
        const float2* F2 = reinterpret_cast<const float2*>(F);
        const size_t aRow0 = (size_t)(rowBase + warp*16 + g) * H_;
        const size_t aRow1 = aRow0 + (size_t)8 * H_;
        const int    aCol  = tq * 2;       // + ks*16 + h*8 + kb

        // B cp.async mapping (256 threads, 64x64 bf16 = 8KB = 512 x 16B)
        const int bRow = tid >> 3;         // 0..31 (+32 for p=1)
        const int bC16 = tid & 7;
        uint32_t bBase[3], bDst[3];
#pragma unroll
        for (int s = 0; s < 3; ++s) {
            bBase[s] = (uint32_t)__cvta_generic_to_shared(BshB + s*BSTAGE);
            bDst[s]  = (uint32_t)__cvta_generic_to_shared(BshB + s*BSTAGE + bRow*APITCH + bC16*8);
        }
        const __nv_bfloat16* gB = g_Wt + (size_t)bRow * H_ + bC16*8;

        // ldmatrix B lane address components (R11-proven formula, quad loop)
        const int lrB = ((lane >> 4) & 1) * 8 + (lane & 7);   // + q*16
        const int lcB = ((lane >> 3) & 1) * 8;                // + ks*16

        // prologue: A f32 pairs for k=0; B stage 0
        float2 avf[16];   // [ks][h][rr] = avf[ks*4 + h*2 + rr]
#pragma unroll
        for (int ks = 0; ks < 4; ++ks)
#pragma unroll
            for (int h = 0; h < 2; ++h) {
                avf[ks*4 + h*2 + 0] = F2[(aRow0 + ks*16 + h*8 + aCol) >> 1];
                avf[ks*4 + h*2 + 1] = F2[(aRow1 + ks*16 + h*8 + aCol) >> 1];
            }
#pragma unroll
        for (int p = 0; p < 2; ++p)
            CP_ASYNC16(bDst[0] + p * 32 * APITCH * 2, gB + (size_t)p * 32 * H_);
        CP_COMMIT();

#pragma unroll 1
        for (int k = 0; k < NITER; ++k) {
            // convert this iter's A pairs to bf16 fragments
            uint32_t afr[4][4];
#pragma unroll
            for (int ks = 0; ks < 4; ++ks)
#pragma unroll
                for (int q = 0; q < 4; ++q) {
                    // fragment order: a0=(g,c) a1=(g+8,c) a2=(g,c+8) a3=(g+8,c+8)
                    // avf layout:  h*2+rr : (h= c-half, rr= row-half)
                    const int idx = ks*4 + ((q >> 1) << 1) + (q & 1);
                    __nv_bfloat162 hv = __floats2bfloat162_rn(avf[idx].x, avf[idx].y);
                    afr[ks][q] = *reinterpret_cast<unsigned*>(&hv);
                }

            // issue B for stage k+1 (3 stages)
            if (k + 1 < NITER) {
                const int kb = (k + 1) * BK;
#pragma unroll
                for (int p = 0; p < 2; ++p)
                    CP_ASYNC16(bDst[(k+1) % 3] + p * 32 * APITCH * 2,
                               gB + (size_t)p * 32 * H_ + kb);
            }
            CP_COMMIT();
            CP_WAIT1();           // B stage k resident
            __syncthreads();      // one barrier per iter (B only)

            // issue next iter's A loads (latency covered by compute below)
            if (k + 1 < NITER) {
                const int kb = (k + 1) * BK;
#pragma unroll
                for (int ks = 0; ks < 4; ++ks)
#pragma unroll
                    for (int h = 0; h < 2; ++h) {
                        avf[ks*4 + h*2 + 0] = F2[(aRow0 + kb + ks*16 + h*8 + aCol) >> 1];
                        avf[ks*4 + h*2 + 1] = F2[(aRow1 + kb + ks*16 + h*8 + aCol) >> 1];
                    }
            }

            const uint32_t bB = bBase[k % 3];
#pragma unroll
            for (int ks = 0; ks < 4; ++ks) {
                uint32_t bfr[8][2];
#pragma unroll
                for (int q = 0; q < 4; ++q) {
                    uint32_t addr = bB + (uint32_t)(((q*16 + lrB)*APITCH + ks*16 + lcB) * 2);
                    ldsm_x4(bfr[q*2][0], bfr[q*2][1], bfr[q*2+1][0], bfr[q*2+1][1], addr);
                }
#pragma unroll
                for (int ni = 0; ni < 8; ++ni) {
                    asm volatile(
                        "mma.sync.aligned.m16n8k16.row.col.f32.bf16.bf16.f32 "
                        "{%0,%1,%2,%3}, {%4,%5,%6,%7}, {%8,%9}, {%0,%1,%2,%3};"
                        : "+f"(acc[ni][0]), "+f"(acc[ni][1]),
                          "+f"(acc[ni][2]), "+f"(acc[ni][3])
                        : "r"(afr[ks][0]), "r"(afr[ks][1]), "r"(afr[ks][2]), "r"(afr[ks][3]),
                          "r"(bfr[ni][0]), "r"(bfr[ni][1]));
                }
            }
        }

        // epilogue: +bias, *log2e
#pragma unroll
        for (int ni = 0; ni < 8; ++ni) {
            int col = ni*8 + tq*2;
            float b0 = bias[col], b1 = bias[col + 1];
            int r0 = rowBase + warp*16 + g;
            float2 v0 = make_float2((acc[ni][0] + b0) * LOG2E,
                                    (acc[ni][1] + b1) * LOG2E);
            float2 v1 = make_float2((acc[ni][2] + b0) * LOG2E,
                                    (acc[ni][3] + b1) * LOG2E);
            *reinterpret_cast<float2*>(&g_emit2[(size_t) r0      * K_ + col]) = v0;
            *reinterpret_cast<float2*>(&g_emit2[(size_t)(r0 + 8) * K_ + col]) = v1;
        }
    }

    // ================= handoff =================
    const int b = blockIdx.x >> 2;
    __threadfence();
    __syncthreads();
    if (tid == 0) s_owner = (atomicAdd(&g_cnt[b], 1) == 3);
    __syncthreads();
    if (!s_owner) return;
    __threadfence();

    // ================= CRF phase (owner block only, R11-proven) ============
    const int len = g_len[b];
    const int*   tg = g_tags + (size_t)b * L_;
    const float* eb = g_emit2 + (size_t)b * L_ * K_;

    {
        float sc = 0.f;
        for (int t = tid; t < len; t += 256) {
            int kt = tg[t];
            sc += eb[t * K_ + kt];
            if (t >= 1) sc += g_Tt2[kt * K_ + tg[t - 1]];
        }
#pragma unroll
        for (int o = 16; o > 0; o >>= 1) sc += __shfl_xor_sync(0xffffffffu, sc, o);
        if (lane == 0) s_red[warp] = sc;
        __syncthreads();
        if (tid == 0) {
            float s = 0.f;
#pragma unroll
            for (int i = 0; i < 8; ++i) s += s_red[i];
            s_score = s;
        }
        __syncthreads();
    }

    if (tid >= 64) return;
    const int j = tid;

    float Erow[64];
    {
        const float4* ep = reinterpret_cast<const float4*>(g_Et + j * K_);
#pragma unroll
        for (int q = 0; q < 16; ++q) {
            float4 v = ep[q];
            Erow[4*q] = v.x; Erow[4*q+1] = v.y; Erow[4*q+2] = v.z; Erow[4*q+3] = v.w;
        }
    }

    ds0[j] = ex2f(eb[j]);
    float C = 0.f;
    float ebuf[8];
#pragma unroll
    for (int q = 0; q < 8; ++q) ebuf[q] = eb[(q + 1) * K_ + j];   // len >= 128
    BAR64();

    int cur = 0;

    auto STEP = [&](int t, int slot, bool renorm, bool use_ring) {
        float ev;
        if (use_ring) {
            ev = ebuf[slot];
            int tn = t + 8; if (tn > L_ - 1) tn = L_ - 1;
            ebuf[slot] = eb[tn * K_ + j];
        } else {
            ev = eb[t * K_ + j];
        }
        const float se = ex2f(ev);

        const float4* p4 = reinterpret_cast<const float4*>(cur ? ds1 : ds0);
        float a0=0.f,a1=0.f,a2=0.f,a3=0.f,a4=0.f,a5=0.f,a6=0.f,a7=0.f;
        float mA = 0.f, mB = 0.f;
#pragma unroll
        for (int q = 0; q < 16; ++q) {
            float4 v = p4[q];
            if (q & 1) {
                a4 = fmaf(v.x, Erow[4*q    ], a4);
                a5 = fmaf(v.y, Erow[4*q + 1], a5);
                a6 = fmaf(v.z, Erow[4*q + 2], a6);
                a7 = fmaf(v.w, Erow[4*q + 3], a7);
            } else {
                a0 = fmaf(v.x, Erow[4*q    ], a0);
                a1 = fmaf(v.y, Erow[4*q + 1], a1);
                a2 = fmaf(v.z, Erow[4*q + 2], a2);
                a3 = fmaf(v.w, Erow[4*q + 3], a3);
            }
            if (renorm) {
                float mv = fmaxf(fmaxf(v.x, v.y), fmaxf(v.z, v.w));
                if (q & 1) mB = fmaxf(mB, mv); else mA = fmaxf(mA, mv);
            }
        }
        float acc = ((a0+a1) + (a2+a3)) + ((a4+a5) + (a6+a7));
        float dn = acc * se;

        if (renorm) {
            float m = fmaxf(fmaxf(mA, mB), 1e-30f);
            dn *= rcpf(m);
            C += lg2f(m);
        }
        (cur ? ds0 : ds1)[j] = dn;
        BAR64();
        cur ^= 1;
    };

#pragma unroll
    for (int t = 1; t <= 7; ++t) STEP(t, t - 1, false, true);

    int tb = 8;
    for (; tb + 8 <= len; tb += 8) {
#pragma unroll
        for (int i = 0; i < 8; ++i)
            STEP(tb + i, (i + 7) & 7, i == 0, true);
    }
    for (int t = tb; t < len; ++t)
        STEP(t, 0, (t & 7) == 0, false);

    float v = (cur ? ds1 : ds0)[j];
#pragma unroll
    for (int o = 16; o > 0; o >>= 1) v += __shfl_xor_sync(0xffffffffu, v, o);
    if (lane == 0) s_red[warp] = v;
    BAR64();
    if (tid == 0) {
        const float S = s_red[0] + s_red[1];
        const float logz2 = C + ESHIFT * (float)(len - 1) + lg2f(S);
        out[b] = (logz2 - s_score) * LN2;
    }
}

// ---------------------------------------------------------------
extern "C" void kernel_launch(void* const* d_in, const int* in_sizes, int n_in,
                              void* d_out, int out_size)
{
    const float*         features = (const float*)d_in[0];
    const float*         W        = (const float*)d_in[1];
    const float*         bias     = (const float*)d_in[2];
    const float*         trans    = (const float*)d_in[3];
    const int*           tagsraw  = (const int*)d_in[4];
    const unsigned char* maskraw  = (const unsigned char*)d_in[5];
    float*               out      = (float*)d_out;

    static int attr_done = 0;
    if (!attr_done) {
        cudaFuncSetAttribute(fused_kernel,
                             cudaFuncAttributeMaxDynamicSharedMemorySize, SMEM_DYN);
        attr_done = 1;
    }

    convert_kernel<<<B_, 256>>>(tagsraw, maskraw, W, trans);
    fused_kernel<<<M_ / BM, 256, SMEM_DYN>>>(features, bias, out);
}

// round 16
// speedup vs baseline: 1.1492x; 1.1492x over previous
#include <cuda_runtime.h>
#include <cuda_bf16.h>
#include <cstdint>

#define B_ 256
#define L_ 512
#define H_ 768
#define K_ 64
#define M_ (B_*L_)

#define LOG2E 1.4426950408889634f
#define LN2   0.6931471805599453f
#define ESHIFT 6.0f

// -------- device scratch --------
__device__ float          g_emit2[M_*K_];     // emit * log2(e)
__device__ float          g_Tt2[K_*K_];       // Tt2[j][k] = T[k][j]*log2e (gold score)
__device__ float          g_Et[K_*K_];        // Et[j][i]  = 2^(T[i][j]*log2e - 6)
__device__ __nv_bfloat16  g_Wt[K_*H_];        // W^T bf16 [n][h]
__device__ int            g_tags[M_];
__device__ int            g_len[B_];
__device__ int            g_cnt[B_];          // per-batch tile completion counter

__device__ __forceinline__ float ex2f(float x){ float y; asm("ex2.approx.ftz.f32 %0, %1;" : "=f"(y) : "f"(x)); return y; }
__device__ __forceinline__ float lg2f(float x){ float y; asm("lg2.approx.f32 %0, %1;"     : "=f"(y) : "f"(x)); return y; }
__device__ __forceinline__ float rcpf(float x){ float y; asm("rcp.approx.ftz.f32 %0, %1;" : "=f"(y) : "f"(x)); return y; }
#define BAR64() asm volatile("bar.sync 1, 64;" ::: "memory")

#define CP_ASYNC16(sa, gp) asm volatile("cp.async.cg.shared.global [%0], [%1], 16;" :: "r"(sa), "l"(gp) : "memory")
#define CP_COMMIT()        asm volatile("cp.async.commit_group;" ::: "memory")
#define CP_WAIT1()         asm volatile("cp.async.wait_group 1;" ::: "memory")

__device__ __forceinline__ void ldsm_x4(uint32_t& r0, uint32_t& r1, uint32_t& r2, uint32_t& r3,
                                        uint32_t addr)
{
    asm volatile("ldmatrix.sync.aligned.m8n8.x4.shared.b16 {%0,%1,%2,%3}, [%4];"
                 : "=r"(r0), "=r"(r1), "=r"(r2), "=r"(r3) : "r"(addr));
}

// ---------------------------------------------------------------
// convert: self-detect dtypes, canonicalize tags, lengths, W/T prep.
__global__ __launch_bounds__(256)
void convert_kernel(const int* __restrict__ tagsraw,
                    const unsigned char* __restrict__ maskraw,
                    const float* __restrict__ W,
                    const float* __restrict__ T)
{
    __shared__ int s_red[8];
    const int b   = blockIdx.x;
    const int tid = threadIdx.x;

    if (tid == 0) g_cnt[b] = 0;            // reset handoff counters every replay

    // dtype self-detect (first 512 tag words, in-bounds under both dtypes)
    unsigned int w = ((const unsigned int*)tagsraw)[2 * tid + 1];
    const int tm = __syncthreads_or(w != 0) ? 0 : 1;
    const int mm = (maskraw[1] != 0) ? 0 : 1;

    for (int t = tid; t < L_; t += 256) {
        long idx = (long)b * L_ + t;
        g_tags[idx] = (tm == 1) ? tagsraw[2 * idx] : tagsraw[idx];
    }
    int cnt = 0;
    if (mm == 0) {
        const unsigned char* mb = maskraw + (size_t)b * L_;
        for (int t = tid; t < L_; t += 256) cnt += (mb[t] != 0);
    } else {
        const unsigned int* mw = ((const unsigned int*)maskraw) + (size_t)b * L_;
        for (int t = tid; t < L_; t += 256) cnt += (mw[t] != 0);
    }
#pragma unroll
    for (int o = 16; o > 0; o >>= 1) cnt += __shfl_xor_sync(0xffffffffu, cnt, o);
    if ((tid & 31) == 0) s_red[tid >> 5] = cnt;
    __syncthreads();
    if (tid == 0) {
        int s = 0;
#pragma unroll
        for (int i = 0; i < 8; ++i) s += s_red[i];
        g_len[b] = s;
    }

    // ---- prep, strided across the whole grid ----
    const int gidx    = b * 256 + tid;
    const int gstride = B_ * 256;
    for (int i = gidx; i < K_*H_; i += gstride) {
        int n = i / H_, h = i - n*H_;
        g_Wt[i] = __float2bfloat16(W[h*K_ + n]);
    }
    for (int i = gidx; i < K_*K_; i += gstride) {
        int j = i >> 6, k = i & 63;
        float t2 = T[k*K_ + j] * LOG2E;
        g_Tt2[i] = t2;
        g_Et[i]  = ex2f(t2 - ESHIFT);
    }
}

// ---------------------------------------------------------------
// FUSED kernel (R11-proven GEMM + CRF) with DEAD-TILE SKIP: block q of
// batch b computes emit rows [128q, 128q+128), which are only read when
// 128q < len[b] -- otherwise the block skips the GEMM phase entirely
// (still participates in the handoff counter).
#define BM      128
#define BK      64
#define NITER   (H_/BK)   // 12
#define APITCH  72        // bf16 per smem row (144B)
#define ASTAGE  (BM*APITCH)
#define BSTAGE  (K_*APITCH)
#define SMEM_DYN ((2*ASTAGE + 3*BSTAGE) * 2)   // bytes

__global__ __launch_bounds__(256, 2)
void fused_kernel(const float* __restrict__ F, const float* __restrict__ bias,
                  float* __restrict__ out)
{
    extern __shared__ __nv_bfloat16 smx[];
    __shared__ float s_red[8];
    __shared__ float ds0[K_], ds1[K_];
    __shared__ float s_score;
    __shared__ int   s_owner;

    __nv_bfloat16* AshB = smx;                 // 2 stages BM x BK
    __nv_bfloat16* BshB = smx + 2*ASTAGE;      // 3 stages K_ x BK

    const int tid  = threadIdx.x;
    const int lane = tid & 31;
    const int warp = tid >> 5;
    const int wm   = warp & 3;
    const int wn   = warp >> 2;
    const int rowBase = blockIdx.x * BM;

    const int b   = blockIdx.x >> 2;
    const int qt  = blockIdx.x & 3;
    const int len = g_len[b];

    // ================= GEMM phase (skipped for dead tiles) =================
    if (qt * BM < len) {
        float acc[2][4][4];
#pragma unroll
        for (int mi = 0; mi < 2; ++mi)
#pragma unroll
            for (int ni = 0; ni < 4; ++ni)
#pragma unroll
                for (int q = 0; q < 4; ++q) acc[mi][ni][q] = 0.f;

        const int aRow = tid >> 4;     // 0..15, rows aRow+16p
        const int aCv  = tid & 15;     // float4 col within BK=64
        const int bRow = tid >> 3;     // 0..31 (+32 for p=1)
        const int bC16 = tid & 7;

        // ldmatrix per-lane address components
        const int lrA = wm*32 + (lane & 15);            // + mi*16
        const int lcA = (lane >> 4) * 8;                // + ks*16
        const int lrB = wn*32 + ((lane >> 4) & 1) * 8 + (lane & 7);   // + np*16
        const int lcB = ((lane >> 3) & 1) * 8;          // + ks*16

        uint32_t aBase[2], bBase[3], bDst[3];
#pragma unroll
        for (int s = 0; s < 2; ++s)
            aBase[s] = (uint32_t)__cvta_generic_to_shared(AshB + s*ASTAGE);
#pragma unroll
        for (int s = 0; s < 3; ++s) {
            bBase[s] = (uint32_t)__cvta_generic_to_shared(BshB + s*BSTAGE);
            bDst[s]  = (uint32_t)__cvta_generic_to_shared(BshB + s*BSTAGE + bRow*APITCH + bC16*8);
        }
        const __nv_bfloat16* gB = g_Wt + (size_t)bRow * H_ + bC16*8;

        float4 av[8];
#pragma unroll
        for (int p = 0; p < 8; ++p)
            av[p] = *reinterpret_cast<const float4*>(
                F + (size_t)(rowBase + aRow + 16*p) * H_ + aCv * 4);
        // prologue: B stage 0
#pragma unroll
        for (int p = 0; p < 2; ++p)
            CP_ASYNC16(bDst[0] + p * 32 * APITCH * 2, gB + (size_t)p * 32 * H_);
        CP_COMMIT();

#pragma unroll 1
        for (int k = 0; k < NITER; ++k) {
            __nv_bfloat16* Ac = AshB + (k & 1) * ASTAGE;

            // stage A (f32 regs -> bf16 smem)
#pragma unroll
            for (int p = 0; p < 8; ++p) {
                int r = aRow + 16*p;
                __nv_bfloat162 h0 = __floats2bfloat162_rn(av[p].x, av[p].y);
                __nv_bfloat162 h1 = __floats2bfloat162_rn(av[p].z, av[p].w);
                uint2 pk = make_uint2(*reinterpret_cast<unsigned*>(&h0),
                                      *reinterpret_cast<unsigned*>(&h1));
                *reinterpret_cast<uint2*>(&Ac[r*APITCH + aCv*4]) = pk;
            }
            // issue B for stage k+1 (3 stages)
            if (k + 1 < NITER) {
                const int kb = (k + 1) * BK;
#pragma unroll
                for (int p = 0; p < 2; ++p)
                    CP_ASYNC16(bDst[(k+1) % 3] + p * 32 * APITCH * 2,
                               gB + (size_t)p * 32 * H_ + kb);
            }
            CP_COMMIT();          // uniform group counting
            CP_WAIT1();           // B stage k resident
            __syncthreads();      // one barrier per iter

            if (k + 1 < NITER) {  // A regs for k+1
                const int kb = (k + 1) * BK;
#pragma unroll
                for (int p = 0; p < 8; ++p)
                    av[p] = *reinterpret_cast<const float4*>(
                        F + (size_t)(rowBase + aRow + 16*p) * H_ + kb + aCv * 4);
            }

            const uint32_t aB = aBase[k & 1];
            const uint32_t bB = bBase[k % 3];
#pragma unroll
            for (int ks = 0; ks < 4; ++ks) {
                uint32_t afr[2][4], bfr[4][2];
#pragma unroll
                for (int mi = 0; mi < 2; ++mi) {
                    uint32_t addr = aB + (uint32_t)(((lrA + mi*16)*APITCH + ks*16 + lcA) * 2);
                    ldsm_x4(afr[mi][0], afr[mi][1], afr[mi][2], afr[mi][3], addr);
                }
#pragma unroll
                for (int np = 0; np < 2; ++np) {
                    uint32_t addr = bB + (uint32_t)(((lrB + np*16)*APITCH + ks*16 + lcB) * 2);
                    ldsm_x4(bfr[np*2][0], bfr[np*2][1], bfr[np*2+1][0], bfr[np*2+1][1], addr);
                }
#pragma unroll
                for (int mi = 0; mi < 2; ++mi)
#pragma unroll
                    for (int ni = 0; ni < 4; ++ni) {
                        asm volatile(
                            "mma.sync.aligned.m16n8k16.row.col.f32.bf16.bf16.f32 "
                            "{%0,%1,%2,%3}, {%4,%5,%6,%7}, {%8,%9}, {%0,%1,%2,%3};"
                            : "+f"(acc[mi][ni][0]), "+f"(acc[mi][ni][1]),
                              "+f"(acc[mi][ni][2]), "+f"(acc[mi][ni][3])
                            : "r"(afr[mi][0]), "r"(afr[mi][1]), "r"(afr[mi][2]), "r"(afr[mi][3]),
                              "r"(bfr[ni][0]), "r"(bfr[ni][1]));
                    }
            }
        }

        const int g2  = lane >> 2;
        const int tq2 = lane & 3;
#pragma unroll
        for (int mi = 0; mi < 2; ++mi) {
#pragma unroll
            for (int ni = 0; ni < 4; ++ni) {
                int col = wn*32 + ni*8 + tq2*2;
                float b0 = bias[col], b1 = bias[col + 1];
                int r0 = rowBase + wm*32 + mi*16 + g2;
                float2 v0 = make_float2((acc[mi][ni][0] + b0) * LOG2E,
                                        (acc[mi][ni][1] + b1) * LOG2E);
                float2 v1 = make_float2((acc[mi][ni][2] + b0) * LOG2E,
                                        (acc[mi][ni][3] + b1) * LOG2E);
                *reinterpret_cast<float2*>(&g_emit2[(size_t) r0      * K_ + col]) = v0;
                *reinterpret_cast<float2*>(&g_emit2[(size_t)(r0 + 8) * K_ + col]) = v1;
            }
        }
    }

    // ================= handoff =================
    __threadfence();
    __syncthreads();
    if (tid == 0) s_owner = (atomicAdd(&g_cnt[b], 1) == 3);
    __syncthreads();
    if (!s_owner) return;
    __threadfence();

    // ================= CRF phase (owner block only, proven) ============
    const int*   tg = g_tags + (size_t)b * L_;
    const float* eb = g_emit2 + (size_t)b * L_ * K_;

    {
        float sc = 0.f;
        for (int t = tid; t < len; t += 256) {
            int kt = tg[t];
            sc += eb[t * K_ + kt];
            if (t >= 1) sc += g_Tt2[kt * K_ + tg[t - 1]];
        }
#pragma unroll
        for (int o = 16; o > 0; o >>= 1) sc += __shfl_xor_sync(0xffffffffu, sc, o);
        if (lane == 0) s_red[warp] = sc;
        __syncthreads();
        if (tid == 0) {
            float s = 0.f;
#pragma unroll
            for (int i = 0; i < 8; ++i) s += s_red[i];
            s_score = s;
        }
        __syncthreads();
    }

    if (tid >= 64) return;
    const int j = tid;

    float Erow[64];
    {
        const float4* ep = reinterpret_cast<const float4*>(g_Et + j * K_);
#pragma unroll
        for (int q = 0; q < 16; ++q) {
            float4 v = ep[q];
            Erow[4*q] = v.x; Erow[4*q+1] = v.y; Erow[4*q+2] = v.z; Erow[4*q+3] = v.w;
        }
    }

    ds0[j] = ex2f(eb[j]);
    float C = 0.f;
    float ebuf[8];
#pragma unroll
    for (int q = 0; q < 8; ++q) ebuf[q] = eb[(q + 1) * K_ + j];   // len >= 128
    BAR64();

    int cur = 0;

    auto STEP = [&](int t, int slot, bool renorm, bool use_ring) {
        float ev;
        if (use_ring) {
            ev = ebuf[slot];
            int tn = t + 8; if (tn > L_ - 1) tn = L_ - 1;
            ebuf[slot] = eb[tn * K_ + j];
        } else {
            ev = eb[t * K_ + j];
        }
        const float se = ex2f(ev);

        const float4* p4 = reinterpret_cast<const float4*>(cur ? ds1 : ds0);
        float a0=0.f,a1=0.f,a2=0.f,a3=0.f,a4=0.f,a5=0.f,a6=0.f,a7=0.f;
        float mA = 0.f, mB = 0.f;
#pragma unroll
        for (int q = 0; q < 16; ++q) {
            float4 v = p4[q];
            if (q & 1) {
                a4 = fmaf(v.x, Erow[4*q    ], a4);
                a5 = fmaf(v.y, Erow[4*q + 1], a5);
                a6 = fmaf(v.z, Erow[4*q + 2], a6);
                a7 = fmaf(v.w, Erow[4*q + 3], a7);
            } else {
                a0 = fmaf(v.x, Erow[4*q    ], a0);
                a1 = fmaf(v.y, Erow[4*q + 1], a1);
                a2 = fmaf(v.z, Erow[4*q + 2], a2);
                a3 = fmaf(v.w, Erow[4*q + 3], a3);
            }
            if (renorm) {
                float mv = fmaxf(fmaxf(v.x, v.y), fmaxf(v.z, v.w));
                if (q & 1) mB = fmaxf(mB, mv); else mA = fmaxf(mA, mv);
            }
        }
        float acc = ((a0+a1) + (a2+a3)) + ((a4+a5) + (a6+a7));
        float dn = acc * se;

        if (renorm) {
            float m = fmaxf(fmaxf(mA, mB), 1e-30f);
            dn *= rcpf(m);
            C += lg2f(m);
        }
        (cur ? ds0 : ds1)[j] = dn;
        BAR64();
        cur ^= 1;
    };

#pragma unroll
    for (int t = 1; t <= 7; ++t) STEP(t, t - 1, false, true);

    int tb = 8;
    for (; tb + 8 <= len; tb += 8) {
#pragma unroll
        for (int i = 0; i < 8; ++i)
            STEP(tb + i, (i + 7) & 7, i == 0, true);
    }
    for (int t = tb; t < len; ++t)
        STEP(t, 0, (t & 7) == 0, false);

    float v = (cur ? ds1 : ds0)[j];
#pragma unroll
    for (int o = 16; o > 0; o >>= 1) v += __shfl_xor_sync(0xffffffffu, v, o);
    if (lane == 0) s_red[warp] = v;
    BAR64();
    if (tid == 0) {
        const float S = s_red[0] + s_red[1];
        const float logz2 = C + ESHIFT * (float)(len - 1) + lg2f(S);
        out[b] = (logz2 - s_score) * LN2;
    }
}

// ---------------------------------------------------------------
extern "C" void kernel_launch(void* const* d_in, const int* in_sizes, int n_in,
                              void* d_out, int out_size)
{
    const float*         features = (const float*)d_in[0];
    const float*         W        = (const float*)d_in[1];
    const float*         bias     = (const float*)d_in[2];
    const float*         trans    = (const float*)d_in[3];
    const int*           tagsraw  = (const int*)d_in[4];
    const unsigned char* maskraw  = (const unsigned char*)d_in[5];
    float*               out      = (float*)d_out;

    static int attr_done = 0;
    if (!attr_done) {
        cudaFuncSetAttribute(fused_kernel,
                             cudaFuncAttributeMaxDynamicSharedMemorySize, SMEM_DYN);
        attr_done = 1;
    }

    convert_kernel<<<B_, 256>>>(tagsraw, maskraw, W, trans);
    fused_kernel<<<M_ / BM, 256, SMEM_DYN>>>(features, bias, out);
}